// round 8
// baseline (speedup 1.0000x reference)
#include <cuda_runtime.h>
#include <cuda_bf16.h>
#include <math.h>
#include <stdint.h>

#define BATCH 4096
#define POSED 13
#define HID 256
#define IN_DIM 269
#define NCTA 128
#define TPB 384
#define GN 16            // n-groups (hidden-dim groups of 16)

// ------------------------- device globals ------------------------------------
__device__ __align__(16) __nv_bfloat16 d_A2[2][BATCH][1024]; // [xh|hh|xl|hl]
__device__ __align__(16) float d_h[BATCH * HID];
__device__ __align__(16) float d_cproj[BATCH * HID];
__device__ __align__(16) __nv_bfloat16 d_Wcat_b[512 * 1536];  // rz: [Bh(x|h) | dup | Bl(x|h)]
__device__ __align__(16) __nv_bfloat16 d_Wihn_b[256 * 768];   // i_n: [Bh|dup|Bl] over x
__device__ __align__(16) __nv_bfloat16 d_Whhn_b[256 * 768];   // h_n over h
__device__ __align__(16) float d_Wctx[256 * 256];
__device__ float d_biasv[1024];
__device__ unsigned g_barcnt;

// ------------------------- helpers -------------------------------------------
__device__ __forceinline__ uint32_t smem_u32(const void* p) {
    uint32_t a;
    asm("{ .reg .u64 t; cvta.to.shared.u64 t, %1; cvt.u32.u64 %0, t; }" : "=r"(a) : "l"(p));
    return a;
}
__device__ __forceinline__ void cp16(uint32_t dst, const void* src) {
    asm volatile("cp.async.cg.shared.global [%0], [%1], 16;" :: "r"(dst), "l"(src) : "memory");
}
#define CP_COMMIT() asm volatile("cp.async.commit_group;" ::: "memory")
#define CP_WAIT1()  asm volatile("cp.async.wait_group 1;" ::: "memory")
#define CP_WAIT0()  asm volatile("cp.async.wait_group 0;" ::: "memory")

__device__ __forceinline__ void bf16_split(float v, __nv_bfloat16& hi, __nv_bfloat16& lo) {
    hi = __float2bfloat16_rn(v);
    lo = __float2bfloat16_rn(v - __bfloat162float(hi));
}
__device__ __forceinline__ void mma_bf16(float* acc, const uint32_t* a, uint32_t b0, uint32_t b1) {
    asm volatile(
        "mma.sync.aligned.m16n8k16.row.col.f32.bf16.bf16.f32 "
        "{%0,%1,%2,%3}, {%4,%5,%6,%7}, {%8,%9}, {%0,%1,%2,%3};"
        : "+f"(acc[0]), "+f"(acc[1]), "+f"(acc[2]), "+f"(acc[3])
        : "r"(a[0]), "r"(a[1]), "r"(a[2]), "r"(a[3]), "r"(b0), "r"(b1));
}
__device__ __forceinline__ void ldm4(uint32_t* f, uint32_t addr) {
    asm volatile("ldmatrix.sync.aligned.m8n8.x4.shared.b16 {%0,%1,%2,%3}, [%4];"
                 : "=r"(f[0]), "=r"(f[1]), "=r"(f[2]), "=r"(f[3]) : "r"(addr));
}

// ------------------------- smem layout ---------------------------------------
struct Smem {
    __nv_bfloat16 sA[2][32][1032];   // staged A pair, row stride 2064B (conflict-free ldm)
    float g2[2][12][16][34];         // per-warp partials [mtile][warp][row][col<=32]
    float cproj[32][256];            // phase-2 rows
    float pose[32][14];
    float sbias[4][16];
};

// ------------------------- prep ----------------------------------------------
__global__ void prep_kernel(const float* __restrict__ W_ih, const float* __restrict__ W_hh,
                            const float* __restrict__ b_ih, const float* __restrict__ b_hh,
                            const float* __restrict__ W_in) {
    int i = blockIdx.x * blockDim.x + threadIdx.x;
    if (i == 0) g_barcnt = 0u;
    if (i < 512 * 1536) {
        int n = i / 1536, col = i % 1536;
        int seg = col >> 9, k = col & 511;
        float w = (k < 256) ? W_ih[n * 256 + k] : W_hh[n * 256 + (k - 256)];
        __nv_bfloat16 hi, lo; bf16_split(w, hi, lo);
        d_Wcat_b[i] = (seg < 2) ? hi : lo;
    }
    if (i < 256 * 768) {
        int n = i / 768, col = i % 768;
        int seg = col >> 8, k = col & 255;
        {
            float w = W_ih[(512 + n) * 256 + k];
            __nv_bfloat16 hi, lo; bf16_split(w, hi, lo);
            d_Wihn_b[i] = (seg < 2) ? hi : lo;
        }
        {
            float w = W_hh[(512 + n) * 256 + k];
            __nv_bfloat16 hi, lo; bf16_split(w, hi, lo);
            d_Whhn_b[i] = (seg < 2) ? hi : lo;
        }
    }
    if (i < 256 * 256) {
        int n = i >> 8, k = i & 255;
        d_Wctx[i] = W_in[n * IN_DIM + POSED + k];
    }
    if (i < 1024) {
        d_biasv[i] = (i < 512) ? (b_ih[i] + b_hh[i])
                   : (i < 768) ? b_ih[i]
                               : b_hh[i - 256];
    }
}

// ------------------------- fp32 GEMM (one-time cproj) ------------------------
__global__ __launch_bounds__(256, 2) void cproj_gemm(const float* __restrict__ context,
                                                     const float* __restrict__ b_in) {
    __shared__ float As[2][16][132];
    __shared__ float Ws[2][16][132];
    const int tid = threadIdx.x;
    const int ty = tid >> 4, tx = tid & 15;
    const int r0 = tid >> 2, kv = (tid & 3) << 2;
    const int m0 = blockIdx.x * 128;
    const int y = blockIdx.y;
    const float* A = context;
    const float* Wt = d_Wctx + y * 128 * 256;
    const float* biasp = b_in + y * 128;
    float* Cp = d_cproj + y * 128;

    float acc[8][8];
#pragma unroll
    for (int i = 0; i < 8; i++)
#pragma unroll
        for (int j = 0; j < 8; j++) acc[i][j] = 0.f;

    const float* Ar0 = A + (size_t)(m0 + r0) * 256 + kv;
    const float* Ar1 = A + (size_t)(m0 + 64 + r0) * 256 + kv;
    const float* Wr0 = Wt + (size_t)r0 * 256 + kv;
    const float* Wr1 = Wt + (size_t)(64 + r0) * 256 + kv;

    float4 pa0 = *(const float4*)Ar0, pa1 = *(const float4*)Ar1;
    float4 pw0 = *(const float4*)Wr0, pw1 = *(const float4*)Wr1;
    As[0][kv+0][r0]=pa0.x; As[0][kv+1][r0]=pa0.y; As[0][kv+2][r0]=pa0.z; As[0][kv+3][r0]=pa0.w;
    As[0][kv+0][64+r0]=pa1.x; As[0][kv+1][64+r0]=pa1.y; As[0][kv+2][64+r0]=pa1.z; As[0][kv+3][64+r0]=pa1.w;
    Ws[0][kv+0][r0]=pw0.x; Ws[0][kv+1][r0]=pw0.y; Ws[0][kv+2][r0]=pw0.z; Ws[0][kv+3][r0]=pw0.w;
    Ws[0][kv+0][64+r0]=pw1.x; Ws[0][kv+1][64+r0]=pw1.y; Ws[0][kv+2][64+r0]=pw1.z; Ws[0][kv+3][64+r0]=pw1.w;
    __syncthreads();

    for (int kt = 0; kt < 16; kt++) {
        const int buf = kt & 1;
        if (kt + 1 < 16) {
            int k0 = (kt + 1) << 4;
            pa0 = *(const float4*)(Ar0 + k0); pa1 = *(const float4*)(Ar1 + k0);
            pw0 = *(const float4*)(Wr0 + k0); pw1 = *(const float4*)(Wr1 + k0);
        }
#pragma unroll
        for (int kk = 0; kk < 16; kk++) {
            float4 a0 = *(const float4*)&As[buf][kk][ty*8];
            float4 a1 = *(const float4*)&As[buf][kk][ty*8+4];
            float4 w0 = *(const float4*)&Ws[buf][kk][tx*8];
            float4 w1 = *(const float4*)&Ws[buf][kk][tx*8+4];
            float af[8]={a0.x,a0.y,a0.z,a0.w,a1.x,a1.y,a1.z,a1.w};
            float wf[8]={w0.x,w0.y,w0.z,w0.w,w1.x,w1.y,w1.z,w1.w};
#pragma unroll
            for (int i = 0; i < 8; i++)
#pragma unroll
                for (int j = 0; j < 8; j++) acc[i][j] += af[i] * wf[j];
        }
        if (kt + 1 < 16) {
            const int nb = buf ^ 1;
            As[nb][kv+0][r0]=pa0.x; As[nb][kv+1][r0]=pa0.y; As[nb][kv+2][r0]=pa0.z; As[nb][kv+3][r0]=pa0.w;
            As[nb][kv+0][64+r0]=pa1.x; As[nb][kv+1][64+r0]=pa1.y; As[nb][kv+2][64+r0]=pa1.z; As[nb][kv+3][64+r0]=pa1.w;
            Ws[nb][kv+0][r0]=pw0.x; Ws[nb][kv+1][r0]=pw0.y; Ws[nb][kv+2][r0]=pw0.z; Ws[nb][kv+3][r0]=pw0.w;
            Ws[nb][kv+0][64+r0]=pw1.x; Ws[nb][kv+1][64+r0]=pw1.y; Ws[nb][kv+2][64+r0]=pw1.z; Ws[nb][kv+3][64+r0]=pw1.w;
            __syncthreads();
        }
    }
#pragma unroll
    for (int i = 0; i < 8; i++) {
        float* crow = Cp + (size_t)(m0 + ty*8 + i) * HID + tx*8;
        float4 b0 = *(const float4*)&biasp[tx*8];
        float4 b1 = *(const float4*)&biasp[tx*8+4];
        *(float4*)crow = make_float4(acc[i][0]+b0.x, acc[i][1]+b0.y, acc[i][2]+b0.z, acc[i][3]+b0.w);
        *(float4*)(crow+4) = make_float4(acc[i][4]+b1.x, acc[i][5]+b1.y, acc[i][6]+b1.z, acc[i][7]+b1.w);
    }
}

// ------------------------- persistent rollout kernel -------------------------
__global__ __launch_bounds__(TPB, 1) void rollout(
    float* __restrict__ out, int T,
    const float* __restrict__ last_pose,
    const float* __restrict__ W_in,
    const float* __restrict__ W_out,
    const float* __restrict__ b_out)
{
    extern __shared__ char smem_raw[];
    Smem* S = (Smem*)smem_raw;

    const int tid = threadIdx.x;
    const int w = tid >> 5;
    const int lane = tid & 31;
    const int cn = blockIdx.x & (GN - 1);
    const int cb = blockIdx.x >> 4;
    const int prow0 = blockIdx.x * 32;      // phase-2 rows

    // -------- persistent smem loads --------
    for (int i = tid; i < 32 * 256; i += TPB)
        S->cproj[i >> 8][i & 255] = d_cproj[(size_t)(prow0 + (i >> 8)) * 256 + (i & 255)];
    if (tid < 64) S->sbias[tid >> 4][tid & 15] = d_biasv[(tid >> 4) * 256 + cn * 16 + (tid & 15)];
    for (int i = tid; i < 32 * 13; i += TPB)
        S->pose[i / 13][i % 13] = last_pose[(size_t)(prow0 + i / 13) * 13 + (i % 13)];

    // -------- warp classes + B-register prologue (64 regs/warp) --------------
    // rz warps 0..7: side = w&1 (0=x,1=h), q = w>>1 (k-quarter). n=32 (r0,r1,z0,z1).
    //   per s(0..3): A hi-frag (xh/hh) -> mma bh AND bl; A lo-frag (xl/hl) -> mma bh.
    // warps 8,9: i_n (x side), q=w-8, 8 s-steps, n=16.  warps 10,11: h_n (h side).
    int aseg_hi, aseg_lo;
    uint32_t breg[64];
    if (w < 8) {
        const int side = w & 1, q = w >> 1;
        aseg_hi = side * 256;
        aseg_lo = 512 + side * 256;
#pragma unroll
        for (int n8t = 0; n8t < 4; n8t++) {
            int nrow = (n8t < 2) ? (cn * 16 + n8t * 8) : (256 + cn * 16 + (n8t - 2) * 8);
            const __nv_bfloat16* rowp = d_Wcat_b + (size_t)(nrow + (lane >> 2)) * 1536 + (lane & 3) * 2;
#pragma unroll
            for (int s = 0; s < 4; s++) {
                int colh = side * 256 + (q * 4 + s) * 16;
                int coll = 1024 + side * 256 + (q * 4 + s) * 16;
                breg[(n8t * 4 + s) * 2]          = *(const uint32_t*)(rowp + colh);
                breg[(n8t * 4 + s) * 2 + 1]      = *(const uint32_t*)(rowp + colh + 8);
                breg[32 + (n8t * 4 + s) * 2]     = *(const uint32_t*)(rowp + coll);
                breg[32 + (n8t * 4 + s) * 2 + 1] = *(const uint32_t*)(rowp + coll + 8);
            }
        }
    } else {
        const int isI = (w < 10);
        const int q = isI ? (w - 8) : (w - 10);
        const __nv_bfloat16* Wb = isI ? d_Wihn_b : d_Whhn_b;
        aseg_hi = isI ? 0 : 256;
        aseg_lo = isI ? 512 : 768;
#pragma unroll
        for (int n8t = 0; n8t < 2; n8t++) {
            int nrow = cn * 16 + n8t * 8;
            const __nv_bfloat16* rowp = Wb + (size_t)(nrow + (lane >> 2)) * 768 + (lane & 3) * 2;
#pragma unroll
            for (int s = 0; s < 8; s++) {
                int colh = (q * 8 + s) * 16;
                int coll = 512 + (q * 8 + s) * 16;
                breg[(n8t * 8 + s) * 2]          = *(const uint32_t*)(rowp + colh);
                breg[(n8t * 8 + s) * 2 + 1]      = *(const uint32_t*)(rowp + colh + 8);
                breg[32 + (n8t * 8 + s) * 2]     = *(const uint32_t*)(rowp + coll);
                breg[32 + (n8t * 8 + s) * 2 + 1] = *(const uint32_t*)(rowp + coll + 8);
            }
        }
    }
    const int qk = (w < 8) ? (w >> 1) : ((w < 10) ? (w - 8) : (w - 10));

    __syncthreads();

    unsigned bar_i = 0;
    auto gridbar = [&]() {
        __syncthreads();
        bar_i++;
        if (tid == 0) {
            __threadfence();
            atomicAdd(&g_barcnt, 1u);
            volatile unsigned* vc = (volatile unsigned*)&g_barcnt;
            unsigned target = bar_i * NCTA;
            while (*vc < target) { }
        }
        __syncthreads();
    };

    // x-projection for phase-2 rows into A buffer `buf` (W_in via L1)
    auto xwrite = [&](int buf) {
        for (int i = tid; i < 32 * 256; i += TPB) {
            int r = i >> 8, j = i & 255;
            float acc = S->cproj[r][j];
            const float* wrow = W_in + (size_t)j * IN_DIM;
#pragma unroll
            for (int k = 0; k < POSED; k++) acc += __ldg(wrow + k) * S->pose[r][k];
            acc = fmaxf(acc, 0.f);
            __nv_bfloat16 hi, lo; bf16_split(acc, hi, lo);
            __nv_bfloat16* Ar = d_A2[buf][prow0 + r];
            Ar[j] = hi;
            Ar[512 + j] = lo;
        }
    };

    // -------- phase 0: h=0, write A buf0 --------
    {
        __nv_bfloat16 z16 = __float2bfloat16_rn(0.f);
        for (int i = tid; i < 32 * 256; i += TPB) {
            int r = i >> 8, j = i & 255;
            d_h[(size_t)(prow0 + r) * 256 + j] = 0.f;
            __nv_bfloat16* Ar = d_A2[0][prow0 + r];
            Ar[256 + j] = z16;
            Ar[768 + j] = z16;
        }
        xwrite(0);
    }
    gridbar();

    // -------- time loop --------
    for (int t = 0; t < T; t++) {
        const int rbuf = t & 1;
        const int wbufA = (t + 1) & 1;
        const __nv_bfloat16* Abase = &d_A2[rbuf][cb * 512][0];

        auto load_pair = [&](int p, int buf) {
            const __nv_bfloat16* src = Abase + (size_t)p * 32 * 1024;
            for (int idx = tid; idx < 4096; idx += TPB) {
                int r = idx >> 7, c = idx & 127;
                cp16(smem_u32(&S->sA[buf][r][c * 8]), src + (size_t)r * 1024 + c * 8);
            }
            CP_COMMIT();
        };

        load_pair(0, 0);

        for (int p = 0; p < 16; p++) {
            const int buf = p & 1;
            if (p + 1 < 16) { load_pair(p + 1, buf ^ 1); CP_WAIT1(); }
            else            { CP_WAIT0(); }
            __syncthreads();   // sA[buf] ready; prev gate pass done (g2 reusable)

            const int m0g = cb * 512 + p * 32;

            // ---- prefetch h_prev for this tile's gate elems ----
            float hp0, hp1 = 0.f;
            {
                int i = tid;
                int grow = m0g + (i >> 8) * 16 + ((i & 255) >> 4);
                hp0 = __ldcg(&d_h[(size_t)grow * 256 + cn * 16 + (i & 15)]);
            }
            if (tid < 128) {
                int i = tid + TPB;
                int grow = m0g + (i >> 8) * 16 + ((i & 255) >> 4);
                hp1 = __ldcg(&d_h[(size_t)grow * 256 + cn * 16 + (i & 15)]);
            }

            // ---- mma ----
            float acc[4][2][4];
#pragma unroll
            for (int a = 0; a < 4; a++)
#pragma unroll
                for (int m = 0; m < 2; m++)
#pragma unroll
                    for (int v = 0; v < 4; v++) acc[a][m][v] = 0.f;

            uint32_t abase = smem_u32(&S->sA[buf][0][0])
                           + (uint32_t)(lane & 15) * 2064u + (uint32_t)((lane >> 4) * 16);

            if (w < 8) {
#pragma unroll
                for (int s = 0; s < 4; s++) {
                    uint32_t adh = abase + (uint32_t)((aseg_hi + (qk * 4 + s) * 16) * 2);
                    uint32_t adl = abase + (uint32_t)((aseg_lo + (qk * 4 + s) * 16) * 2);
                    uint32_t fh0[4], fh1[4], fl0[4], fl1[4];
                    ldm4(fh0, adh);
                    ldm4(fh1, adh + 16u * 2064u);
                    ldm4(fl0, adl);
                    ldm4(fl1, adl + 16u * 2064u);
#pragma unroll
                    for (int n8t = 0; n8t < 4; n8t++) {
                        uint32_t bh0 = breg[(n8t * 4 + s) * 2],     bh1 = breg[(n8t * 4 + s) * 2 + 1];
                        uint32_t bl0 = breg[32 + (n8t * 4 + s) * 2], bl1 = breg[32 + (n8t * 4 + s) * 2 + 1];
                        mma_bf16(acc[n8t][0], fh0, bh0, bh1);
                        mma_bf16(acc[n8t][1], fh1, bh0, bh1);
                        mma_bf16(acc[n8t][0], fl0, bh0, bh1);
                        mma_bf16(acc[n8t][1], fl1, bh0, bh1);
                        mma_bf16(acc[n8t][0], fh0, bl0, bl1);
                        mma_bf16(acc[n8t][1], fh1, bl0, bl1);
                    }
                }
            } else {
#pragma unroll
                for (int s = 0; s < 8; s++) {
                    uint32_t adh = abase + (uint32_t)((aseg_hi + (qk * 8 + s) * 16) * 2);
                    uint32_t adl = abase + (uint32_t)((aseg_lo + (qk * 8 + s) * 16) * 2);
                    uint32_t fh0[4], fh1[4], fl0[4], fl1[4];
                    ldm4(fh0, adh);
                    ldm4(fh1, adh + 16u * 2064u);
                    ldm4(fl0, adl);
                    ldm4(fl1, adl + 16u * 2064u);
#pragma unroll
                    for (int n8t = 0; n8t < 2; n8t++) {
                        uint32_t bh0 = breg[(n8t * 8 + s) * 2],     bh1 = breg[(n8t * 8 + s) * 2 + 1];
                        uint32_t bl0 = breg[32 + (n8t * 8 + s) * 2], bl1 = breg[32 + (n8t * 8 + s) * 2 + 1];
                        mma_bf16(acc[n8t][0], fh0, bh0, bh1);
                        mma_bf16(acc[n8t][1], fh1, bh0, bh1);
                        mma_bf16(acc[n8t][0], fl0, bh0, bh1);
                        mma_bf16(acc[n8t][1], fl1, bh0, bh1);
                        mma_bf16(acc[n8t][0], fh0, bl0, bl1);
                        mma_bf16(acc[n8t][1], fh1, bl0, bl1);
                    }
                }
            }

            // ---- write per-warp partials (deterministic) ----
            {
                int gr = lane >> 2, gc = (lane & 3) << 1;
                const int nmax = (w < 8) ? 4 : 2;
#pragma unroll
                for (int n8t = 0; n8t < 4; n8t++) {
                    if (n8t >= nmax) break;
#pragma unroll
                    for (int m = 0; m < 2; m++) {
                        *(float2*)&S->g2[m][w][gr][n8t * 8 + gc]     = make_float2(acc[n8t][m][0], acc[n8t][m][1]);
                        *(float2*)&S->g2[m][w][gr + 8][n8t * 8 + gc] = make_float2(acc[n8t][m][2], acc[n8t][m][3]);
                    }
                }
            }
            __syncthreads();   // partials complete; sA[buf] free

            // ---- gates: 32 rows x 16 dims, fixed-order sums ----
#pragma unroll
            for (int rep = 0; rep < 2; rep++) {
                int i = tid + rep * TPB;
                if (rep == 1 && tid >= 128) break;
                float hp = (rep == 0) ? hp0 : hp1;
                int mt = i >> 8, sub = i & 255;
                int r16 = sub >> 4, dl = sub & 15;
                int grow = m0g + mt * 16 + r16;
                int dim = cn * 16 + dl;
                float sr = S->g2[mt][0][r16][dl];
                float sz = S->g2[mt][0][r16][16 + dl];
#pragma unroll
                for (int ww = 1; ww < 8; ww++) {
                    sr += S->g2[mt][ww][r16][dl];
                    sz += S->g2[mt][ww][r16][16 + dl];
                }
                sr += S->sbias[0][dl];
                sz += S->sbias[1][dl];
                float in_ = S->g2[mt][8][r16][dl]  + S->g2[mt][9][r16][dl]  + S->sbias[2][dl];
                float hn  = S->g2[mt][10][r16][dl] + S->g2[mt][11][r16][dl] + S->sbias[3][dl];
                float r = 1.f / (1.f + expf(-sr));
                float z = 1.f / (1.f + expf(-sz));
                float n = tanhf(in_ + r * hn);
                float hnew = (1.f - z) * n + z * hp;
                d_h[(size_t)grow * 256 + dim] = hnew;
                __nv_bfloat16 hi, lo; bf16_split(hnew, hi, lo);
                __nv_bfloat16* Ar = d_A2[wbufA][grow];
                Ar[256 + dim] = hi;
                Ar[768 + dim] = lo;
            }
        }
        gridbar();

        // -------- phase 2: pose update + next x --------
        for (int rloc = w; rloc < 32; rloc += 12) {
            int grow = prow0 + rloc;
            const float* hrow = d_h + (size_t)grow * 256;
            float hreg[8];
#pragma unroll
            for (int i = 0; i < 8; i++) hreg[i] = __ldcg(hrow + lane + 32 * i);
#pragma unroll
            for (int pp = 0; pp < POSED; pp++) {
                float dp = 0.f;
#pragma unroll
                for (int i = 0; i < 8; i++) dp += __ldg(&W_out[pp * 256 + lane + 32 * i]) * hreg[i];
#pragma unroll
                for (int o = 16; o > 0; o >>= 1) dp += __shfl_down_sync(0xffffffffu, dp, o);
                if (lane == 0) S->pose[rloc][pp] += dp + b_out[pp];
            }
            __syncwarp();
            if (lane == 0) {
                float q = sqrtf(S->pose[rloc][3] * S->pose[rloc][3] +
                                S->pose[rloc][4] * S->pose[rloc][4] +
                                S->pose[rloc][5] * S->pose[rloc][5] +
                                S->pose[rloc][6] * S->pose[rloc][6]);
                q = fmaxf(q, 1e-12f);
                S->pose[rloc][3] /= q;
                S->pose[rloc][4] /= q;
                S->pose[rloc][5] /= q;
                S->pose[rloc][6] /= q;
                float* op = out + ((size_t)grow * T + t) * POSED;
#pragma unroll
                for (int pp = 0; pp < POSED; pp++) op[pp] = S->pose[rloc][pp];
            }
        }
        __syncthreads();
        xwrite(wbufA);
        gridbar();
    }
}

// ------------------------- launch --------------------------------------------
extern "C" void kernel_launch(void* const* d_in, const int* in_sizes, int n_in,
                              void* d_out, int out_size)
{
    const float* last_pose = (const float*)d_in[0];
    const float* context   = (const float*)d_in[1];
    const float* W_in  = (const float*)d_in[3];
    const float* b_in  = (const float*)d_in[4];
    const float* W_ih  = (const float*)d_in[5];
    const float* b_ih  = (const float*)d_in[6];
    const float* W_hh  = (const float*)d_in[7];
    const float* b_hh  = (const float*)d_in[8];
    const float* W_out = (const float*)d_in[9];
    const float* b_out = (const float*)d_in[10];
    float* out = (float*)d_out;

    const int T = out_size / (BATCH * POSED);
    const int smem_bytes = (int)sizeof(Smem);

    cudaFuncSetAttribute(rollout, cudaFuncAttributeMaxDynamicSharedMemorySize, smem_bytes);

    prep_kernel<<<(512 * 1536 + 255) / 256, 256>>>(W_ih, W_hh, b_ih, b_hh, W_in);
    cproj_gemm<<<dim3(BATCH / 128, 2), 256>>>(context, b_in);
    rollout<<<NCTA, TPB, smem_bytes>>>(out, T, last_pose, W_in, W_out, b_out);
}

// round 9
// speedup vs baseline: 1.5673x; 1.5673x over previous
#include <cuda_runtime.h>
#include <cuda_bf16.h>
#include <math.h>
#include <stdint.h>

#define BATCH 4096
#define POSED 13
#define HID 256
#define IN_DIM 269
#define NCTA 128
#define TPB 384
#define GN 16            // n-groups (hidden-dim groups of 16)

// ------------------------- device globals ------------------------------------
__device__ __align__(16) __nv_bfloat16 d_A2[2][BATCH][1024]; // [xh|hh|xl|hl]
__device__ __align__(16) float d_h[BATCH * HID];
__device__ __align__(16) float d_cproj[BATCH * HID];
__device__ __align__(16) __nv_bfloat16 d_Wcat_b[512 * 1536];  // rz: [Bh(x|h)|Bh dup|Bl(x|h)]
__device__ __align__(16) __nv_bfloat16 d_Wihn_b[256 * 768];   // i_n: [Bh|Bh|Bl] over x
__device__ __align__(16) __nv_bfloat16 d_Whhn_b[256 * 768];   // h_n over h
__device__ __align__(16) float d_Wctx[256 * 256];
__device__ float d_biasv[1024];
__device__ unsigned g_barcnt;

// ------------------------- helpers -------------------------------------------
__device__ __forceinline__ uint32_t smem_u32(const void* p) {
    uint32_t a;
    asm("{ .reg .u64 t; cvta.to.shared.u64 t, %1; cvt.u32.u64 %0, t; }" : "=r"(a) : "l"(p));
    return a;
}
__device__ __forceinline__ void cp16(uint32_t dst, const void* src) {
    asm volatile("cp.async.cg.shared.global [%0], [%1], 16;" :: "r"(dst), "l"(src) : "memory");
}
#define CP_COMMIT() asm volatile("cp.async.commit_group;" ::: "memory")
#define CP_WAIT1()  asm volatile("cp.async.wait_group 1;" ::: "memory")
#define CP_WAIT0()  asm volatile("cp.async.wait_group 0;" ::: "memory")

__device__ __forceinline__ void bf16_split(float v, __nv_bfloat16& hi, __nv_bfloat16& lo) {
    hi = __float2bfloat16_rn(v);
    lo = __float2bfloat16_rn(v - __bfloat162float(hi));
}
__device__ __forceinline__ void mma_bf16(float* acc, const uint32_t* a, uint32_t b0, uint32_t b1) {
    asm volatile(
        "mma.sync.aligned.m16n8k16.row.col.f32.bf16.bf16.f32 "
        "{%0,%1,%2,%3}, {%4,%5,%6,%7}, {%8,%9}, {%0,%1,%2,%3};"
        : "+f"(acc[0]), "+f"(acc[1]), "+f"(acc[2]), "+f"(acc[3])
        : "r"(a[0]), "r"(a[1]), "r"(a[2]), "r"(a[3]), "r"(b0), "r"(b1));
}
__device__ __forceinline__ void ldm4(uint32_t* f, uint32_t addr) {
    asm volatile("ldmatrix.sync.aligned.m8n8.x4.shared.b16 {%0,%1,%2,%3}, [%4];"
                 : "=r"(f[0]), "=r"(f[1]), "=r"(f[2]), "=r"(f[3]) : "r"(addr));
}

// ------------------------- smem layout ---------------------------------------
struct Smem {
    __nv_bfloat16 sA[2][32][1032];   // staged A pair (32 rows x 1024 + pad)
    float g2[2][12][16][8];          // per-warp mma partials [mtile][warp][row][col]
    float wp[256][14];               // W_in[:, :13]
    float wout[13][256];
    float cproj[32][256];            // phase-2 rows
    float pose[32][14];
    float sbias[4][16];
};

// ------------------------- prep ----------------------------------------------
__global__ void prep_kernel(const float* __restrict__ W_ih, const float* __restrict__ W_hh,
                            const float* __restrict__ b_ih, const float* __restrict__ b_hh,
                            const float* __restrict__ W_in) {
    int i = blockIdx.x * blockDim.x + threadIdx.x;
    if (i == 0) g_barcnt = 0u;
    if (i < 512 * 1536) {
        int n = i / 1536, col = i % 1536;
        int seg = col >> 9, k = col & 511;
        float w = (k < 256) ? W_ih[n * 256 + k] : W_hh[n * 256 + (k - 256)];
        __nv_bfloat16 hi, lo; bf16_split(w, hi, lo);
        d_Wcat_b[i] = (seg < 2) ? hi : lo;
    }
    if (i < 256 * 768) {
        int n = i / 768, col = i % 768;
        int seg = col >> 8, k = col & 255;
        {
            float w = W_ih[(512 + n) * 256 + k];
            __nv_bfloat16 hi, lo; bf16_split(w, hi, lo);
            d_Wihn_b[i] = (seg < 2) ? hi : lo;
        }
        {
            float w = W_hh[(512 + n) * 256 + k];
            __nv_bfloat16 hi, lo; bf16_split(w, hi, lo);
            d_Whhn_b[i] = (seg < 2) ? hi : lo;
        }
    }
    if (i < 256 * 256) {
        int n = i >> 8, k = i & 255;
        d_Wctx[i] = W_in[n * IN_DIM + POSED + k];
    }
    if (i < 1024) {
        d_biasv[i] = (i < 512) ? (b_ih[i] + b_hh[i])
                   : (i < 768) ? b_ih[i]
                               : b_hh[i - 256];
    }
}

// ------------------------- fp32 GEMM (one-time cproj) ------------------------
__global__ __launch_bounds__(256, 2) void cproj_gemm(const float* __restrict__ context,
                                                     const float* __restrict__ b_in) {
    __shared__ float As[2][16][132];
    __shared__ float Ws[2][16][132];
    const int tid = threadIdx.x;
    const int ty = tid >> 4, tx = tid & 15;
    const int r0 = tid >> 2, kv = (tid & 3) << 2;
    const int m0 = blockIdx.x * 128;
    const int y = blockIdx.y;
    const float* A = context;
    const float* Wt = d_Wctx + y * 128 * 256;
    const float* biasp = b_in + y * 128;
    float* Cp = d_cproj + y * 128;

    float acc[8][8];
#pragma unroll
    for (int i = 0; i < 8; i++)
#pragma unroll
        for (int j = 0; j < 8; j++) acc[i][j] = 0.f;

    const float* Ar0 = A + (size_t)(m0 + r0) * 256 + kv;
    const float* Ar1 = A + (size_t)(m0 + 64 + r0) * 256 + kv;
    const float* Wr0 = Wt + (size_t)r0 * 256 + kv;
    const float* Wr1 = Wt + (size_t)(64 + r0) * 256 + kv;

    float4 pa0 = *(const float4*)Ar0, pa1 = *(const float4*)Ar1;
    float4 pw0 = *(const float4*)Wr0, pw1 = *(const float4*)Wr1;
    As[0][kv+0][r0]=pa0.x; As[0][kv+1][r0]=pa0.y; As[0][kv+2][r0]=pa0.z; As[0][kv+3][r0]=pa0.w;
    As[0][kv+0][64+r0]=pa1.x; As[0][kv+1][64+r0]=pa1.y; As[0][kv+2][64+r0]=pa1.z; As[0][kv+3][64+r0]=pa1.w;
    Ws[0][kv+0][r0]=pw0.x; Ws[0][kv+1][r0]=pw0.y; Ws[0][kv+2][r0]=pw0.z; Ws[0][kv+3][r0]=pw0.w;
    Ws[0][kv+0][64+r0]=pw1.x; Ws[0][kv+1][64+r0]=pw1.y; Ws[0][kv+2][64+r0]=pw1.z; Ws[0][kv+3][64+r0]=pw1.w;
    __syncthreads();

    for (int kt = 0; kt < 16; kt++) {
        const int buf = kt & 1;
        if (kt + 1 < 16) {
            int k0 = (kt + 1) << 4;
            pa0 = *(const float4*)(Ar0 + k0); pa1 = *(const float4*)(Ar1 + k0);
            pw0 = *(const float4*)(Wr0 + k0); pw1 = *(const float4*)(Wr1 + k0);
        }
#pragma unroll
        for (int kk = 0; kk < 16; kk++) {
            float4 a0 = *(const float4*)&As[buf][kk][ty*8];
            float4 a1 = *(const float4*)&As[buf][kk][ty*8+4];
            float4 w0 = *(const float4*)&Ws[buf][kk][tx*8];
            float4 w1 = *(const float4*)&Ws[buf][kk][tx*8+4];
            float af[8]={a0.x,a0.y,a0.z,a0.w,a1.x,a1.y,a1.z,a1.w};
            float wf[8]={w0.x,w0.y,w0.z,w0.w,w1.x,w1.y,w1.z,w1.w};
#pragma unroll
            for (int i = 0; i < 8; i++)
#pragma unroll
                for (int j = 0; j < 8; j++) acc[i][j] += af[i] * wf[j];
        }
        if (kt + 1 < 16) {
            const int nb = buf ^ 1;
            As[nb][kv+0][r0]=pa0.x; As[nb][kv+1][r0]=pa0.y; As[nb][kv+2][r0]=pa0.z; As[nb][kv+3][r0]=pa0.w;
            As[nb][kv+0][64+r0]=pa1.x; As[nb][kv+1][64+r0]=pa1.y; As[nb][kv+2][64+r0]=pa1.z; As[nb][kv+3][64+r0]=pa1.w;
            Ws[nb][kv+0][r0]=pw0.x; Ws[nb][kv+1][r0]=pw0.y; Ws[nb][kv+2][r0]=pw0.z; Ws[nb][kv+3][r0]=pw0.w;
            Ws[nb][kv+0][64+r0]=pw1.x; Ws[nb][kv+1][64+r0]=pw1.y; Ws[nb][kv+2][64+r0]=pw1.z; Ws[nb][kv+3][64+r0]=pw1.w;
            __syncthreads();
        }
    }
#pragma unroll
    for (int i = 0; i < 8; i++) {
        float* crow = Cp + (size_t)(m0 + ty*8 + i) * HID + tx*8;
        float4 b0 = *(const float4*)&biasp[tx*8];
        float4 b1 = *(const float4*)&biasp[tx*8+4];
        *(float4*)crow = make_float4(acc[i][0]+b0.x, acc[i][1]+b0.y, acc[i][2]+b0.z, acc[i][3]+b0.w);
        *(float4*)(crow+4) = make_float4(acc[i][4]+b1.x, acc[i][5]+b1.y, acc[i][6]+b1.z, acc[i][7]+b1.w);
    }
}

// ------------------------- persistent rollout kernel -------------------------
__global__ __launch_bounds__(TPB, 1) void rollout(
    float* __restrict__ out, int T,
    const float* __restrict__ last_pose,
    const float* __restrict__ W_in,
    const float* __restrict__ W_out,
    const float* __restrict__ b_out)
{
    extern __shared__ char smem_raw[];
    Smem* S = (Smem*)smem_raw;

    const int tid = threadIdx.x;
    const int w = tid >> 5;
    const int lane = tid & 31;
    const int cn = blockIdx.x & (GN - 1);
    const int cb = blockIdx.x >> 4;
    const int prow0 = blockIdx.x * 32;      // phase-2 rows

    // -------- persistent smem loads --------
    for (int i = tid; i < 256 * 13; i += TPB)
        S->wp[i / 13][i % 13] = W_in[(size_t)(i / 13) * IN_DIM + (i % 13)];
    for (int i = tid; i < 13 * 256; i += TPB)
        S->wout[i >> 8][i & 255] = W_out[i];
    for (int i = tid; i < 32 * 256; i += TPB)
        S->cproj[i >> 8][i & 255] = d_cproj[(size_t)(prow0 + (i >> 8)) * 256 + (i & 255)];
    if (tid < 64) S->sbias[tid >> 4][tid & 15] = d_biasv[(tid >> 4) * 256 + cn * 16 + (tid & 15)];
    for (int i = tid; i < 32 * 13; i += TPB)
        S->pose[i / 13][i % 13] = last_pose[(size_t)(prow0 + i / 13) * 13 + (i % 13)];

    // -------- warp class setup + B-register prologue (64 regs/warp) ----------
    // rz warps 0..7: tile = w>>1 (0,1 = r dims 0-7/8-15; 2,3 = z), half = w&1
    //   half 0 = x contributions, half 1 = h contributions.
    // warps 8,9: i_n dims 0-7/8-15 (x only).  warps 10,11: h_n (h only).
    // Per iteration s (16 total): A hi-frag -> bh AND bl; A lo-frag -> bh.
    const __nv_bfloat16* wsrc; int ldw, nrow;
    int ca0, ca1, cb0, cb1;
    if (w < 8) {
        int tile = w >> 1, xh = w & 1;   // xh==0 -> x half, xh==1 -> h half
        wsrc = d_Wcat_b; ldw = 1536;
        nrow = (tile < 2) ? (cn * 16 + tile * 8) : (256 + cn * 16 + (tile - 2) * 8);
        if (xh == 0) { ca0 = 0;   ca1 = 512; cb0 = 0;   cb1 = 1024; }
        else         { ca0 = 256; ca1 = 768; cb0 = 256; cb1 = 1280; }
    } else if (w < 10) {
        wsrc = d_Wihn_b; ldw = 768; nrow = cn * 16 + (w - 8) * 8;
        ca0 = 0; ca1 = 512; cb0 = 0; cb1 = 512;
    } else {
        wsrc = d_Whhn_b; ldw = 768; nrow = cn * 16 + (w - 10) * 8;
        ca0 = 256; ca1 = 768; cb0 = 0; cb1 = 512;
    }
    uint32_t breg[64];
    {
        const __nv_bfloat16* wbrow = wsrc + (size_t)(nrow + (lane >> 2)) * ldw + (lane & 3) * 2;
#pragma unroll
        for (int s = 0; s < 16; s++) {
            breg[2 * s]          = *(const uint32_t*)(wbrow + cb0 + s * 16);
            breg[2 * s + 1]      = *(const uint32_t*)(wbrow + cb0 + s * 16 + 8);
            breg[32 + 2 * s]     = *(const uint32_t*)(wbrow + cb1 + s * 16);
            breg[32 + 2 * s + 1] = *(const uint32_t*)(wbrow + cb1 + s * 16 + 8);
        }
    }

    __syncthreads();

    unsigned bar_i = 0;
    auto gridbar = [&]() {
        __syncthreads();
        bar_i++;
        if (tid == 0) {
            __threadfence();
            atomicAdd(&g_barcnt, 1u);
            volatile unsigned* vc = (volatile unsigned*)&g_barcnt;
            unsigned target = bar_i * NCTA;
            while (*vc < target) { }
        }
        __syncthreads();
    };

    // x-projection for phase-2 rows into A buffer `buf`
    auto xwrite = [&](int buf) {
        for (int i = tid; i < 32 * 256; i += TPB) {
            int r = i >> 8, j = i & 255;
            float acc = S->cproj[r][j];
#pragma unroll
            for (int k = 0; k < POSED; k++) acc += S->wp[j][k] * S->pose[r][k];
            acc = fmaxf(acc, 0.f);
            __nv_bfloat16 hi, lo; bf16_split(acc, hi, lo);
            __nv_bfloat16* Ar = d_A2[buf][prow0 + r];
            Ar[j] = hi;
            Ar[512 + j] = lo;
        }
    };

    // -------- phase 0: h=0, write A buf0 --------
    {
        __nv_bfloat16 z16 = __float2bfloat16_rn(0.f);
        for (int i = tid; i < 32 * 256; i += TPB) {
            int r = i >> 8, j = i & 255;
            d_h[(size_t)(prow0 + r) * 256 + j] = 0.f;
            __nv_bfloat16* Ar = d_A2[0][prow0 + r];
            Ar[256 + j] = z16;
            Ar[768 + j] = z16;
        }
        xwrite(0);
    }
    gridbar();

    // -------- time loop --------
    for (int t = 0; t < T; t++) {
        const int rbuf = t & 1;
        const int wbufA = (t + 1) & 1;
        const __nv_bfloat16* Abase = &d_A2[rbuf][cb * 512][0];

        auto load_pair = [&](int p, int buf) {
            const __nv_bfloat16* src = Abase + (size_t)p * 32 * 1024;
            for (int idx = tid; idx < 4096; idx += TPB) {
                int r = idx >> 7, c = idx & 127;
                cp16(smem_u32(&S->sA[buf][r][c * 8]), src + (size_t)r * 1024 + c * 8);
            }
            CP_COMMIT();
        };

        load_pair(0, 0);

        for (int p = 0; p < 16; p++) {
            const int buf = p & 1;
            if (p + 1 < 16) { load_pair(p + 1, buf ^ 1); CP_WAIT1(); }
            else            { CP_WAIT0(); }
            __syncthreads();   // sA[buf] ready; prev gate pass done (g2 reusable)

            const int m0g = cb * 512 + p * 32;

            // ---- prefetch h_prev for this tile's gate elems (hide latency) ----
            float hp0, hp1 = 0.f;
            {
                int i = tid;
                int grow = m0g + (i >> 8) * 16 + ((i & 255) >> 4);
                hp0 = __ldcg(&d_h[(size_t)grow * 256 + cn * 16 + (i & 15)]);
            }
            if (tid < 128) {
                int i = tid + TPB;
                int grow = m0g + (i >> 8) * 16 + ((i & 255) >> 4);
                hp1 = __ldcg(&d_h[(size_t)grow * 256 + cn * 16 + (i & 15)]);
            }

            // ---- mma: 16 iters, hi-frag reused for bh and bl ----
            float acc0[4] = {0.f, 0.f, 0.f, 0.f};
            float acc1[4] = {0.f, 0.f, 0.f, 0.f};
            uint32_t abase = smem_u32(&S->sA[buf][0][0])
                           + (uint32_t)(lane & 15) * 2064u + (uint32_t)((lane >> 4) * 16);
#pragma unroll
            for (int s = 0; s < 16; s++) {
                uint32_t adh = abase + (uint32_t)((ca0 + s * 16) * 2);
                uint32_t adl = abase + (uint32_t)((ca1 + s * 16) * 2);
                uint32_t bh0 = breg[2 * s],      bh1 = breg[2 * s + 1];
                uint32_t bl0 = breg[32 + 2 * s], bl1 = breg[32 + 2 * s + 1];
                uint32_t fh0[4], fh1[4], fl0[4], fl1[4];
                ldm4(fh0, adh);
                ldm4(fh1, adh + 16u * 2064u);
                ldm4(fl0, adl);
                ldm4(fl1, adl + 16u * 2064u);
                mma_bf16(acc0, fh0, bh0, bh1);
                mma_bf16(acc1, fh1, bh0, bh1);
                mma_bf16(acc0, fl0, bh0, bh1);
                mma_bf16(acc1, fl1, bh0, bh1);
                mma_bf16(acc0, fh0, bl0, bl1);
                mma_bf16(acc1, fh1, bl0, bl1);
            }

            // ---- write per-warp partials (deterministic; no atomics) ----
            {
                int gr = lane >> 2, gc = (lane & 3) << 1;
                *(float2*)&S->g2[0][w][gr][gc]     = make_float2(acc0[0], acc0[1]);
                *(float2*)&S->g2[0][w][gr + 8][gc] = make_float2(acc0[2], acc0[3]);
                *(float2*)&S->g2[1][w][gr][gc]     = make_float2(acc1[0], acc1[1]);
                *(float2*)&S->g2[1][w][gr + 8][gc] = make_float2(acc1[2], acc1[3]);
            }
            __syncthreads();   // mma+partials done; sA[buf] free; g2 complete

            // ---- gates for 32 rows x 16 dims (fixed-order sums) ----
#pragma unroll
            for (int rep = 0; rep < 2; rep++) {
                int i = tid + rep * TPB;
                if (rep == 1 && tid >= 128) break;
                float hp = (rep == 0) ? hp0 : hp1;
                int mt = i >> 8, sub = i & 255;
                int r16 = sub >> 4, dl = sub & 15;
                int cg = dl >> 3, c = dl & 7;
                int grow = m0g + mt * 16 + r16;
                int dim = cn * 16 + dl;
                float sr  = S->g2[mt][2 * cg][r16][c]     + S->g2[mt][2 * cg + 1][r16][c] + S->sbias[0][dl];
                float sz  = S->g2[mt][4 + 2 * cg][r16][c] + S->g2[mt][5 + 2 * cg][r16][c] + S->sbias[1][dl];
                float in_ = S->g2[mt][8 + cg][r16][c]  + S->sbias[2][dl];
                float hn  = S->g2[mt][10 + cg][r16][c] + S->sbias[3][dl];
                float r = 1.f / (1.f + expf(-sr));
                float z = 1.f / (1.f + expf(-sz));
                float n = tanhf(in_ + r * hn);
                float hnew = (1.f - z) * n + z * hp;
                d_h[(size_t)grow * 256 + dim] = hnew;
                __nv_bfloat16 hi, lo; bf16_split(hnew, hi, lo);
                __nv_bfloat16* Ar = d_A2[wbufA][grow];
                Ar[256 + dim] = hi;
                Ar[768 + dim] = lo;
            }
            // next iteration's first __syncthreads protects g2 reuse
        }
        gridbar();

        // -------- phase 2: pose update + next x --------
        for (int rloc = w; rloc < 32; rloc += 12) {
            int grow = prow0 + rloc;
            const float* hrow = d_h + (size_t)grow * 256;
            float hreg[8];
#pragma unroll
            for (int i = 0; i < 8; i++) hreg[i] = __ldcg(hrow + lane + 32 * i);
#pragma unroll
            for (int pp = 0; pp < POSED; pp++) {
                float dp = 0.f;
#pragma unroll
                for (int i = 0; i < 8; i++) dp += S->wout[pp][lane + 32 * i] * hreg[i];
#pragma unroll
                for (int o = 16; o > 0; o >>= 1) dp += __shfl_down_sync(0xffffffffu, dp, o);
                if (lane == 0) S->pose[rloc][pp] += dp + b_out[pp];
            }
            __syncwarp();
            if (lane == 0) {
                float q = sqrtf(S->pose[rloc][3] * S->pose[rloc][3] +
                                S->pose[rloc][4] * S->pose[rloc][4] +
                                S->pose[rloc][5] * S->pose[rloc][5] +
                                S->pose[rloc][6] * S->pose[rloc][6]);
                q = fmaxf(q, 1e-12f);
                S->pose[rloc][3] /= q;
                S->pose[rloc][4] /= q;
                S->pose[rloc][5] /= q;
                S->pose[rloc][6] /= q;
                float* op = out + ((size_t)grow * T + t) * POSED;
#pragma unroll
                for (int pp = 0; pp < POSED; pp++) op[pp] = S->pose[rloc][pp];
            }
        }
        __syncthreads();
        xwrite(wbufA);
        gridbar();
    }
}

// ------------------------- launch --------------------------------------------
extern "C" void kernel_launch(void* const* d_in, const int* in_sizes, int n_in,
                              void* d_out, int out_size)
{
    const float* last_pose = (const float*)d_in[0];
    const float* context   = (const float*)d_in[1];
    const float* W_in  = (const float*)d_in[3];
    const float* b_in  = (const float*)d_in[4];
    const float* W_ih  = (const float*)d_in[5];
    const float* b_ih  = (const float*)d_in[6];
    const float* W_hh  = (const float*)d_in[7];
    const float* b_hh  = (const float*)d_in[8];
    const float* W_out = (const float*)d_in[9];
    const float* b_out = (const float*)d_in[10];
    float* out = (float*)d_out;

    const int T = out_size / (BATCH * POSED);
    const int smem_bytes = (int)sizeof(Smem);

    cudaFuncSetAttribute(rollout, cudaFuncAttributeMaxDynamicSharedMemorySize, smem_bytes);

    prep_kernel<<<(512 * 1536 + 255) / 256, 256>>>(W_ih, W_hh, b_ih, b_hh, W_in);
    cproj_gemm<<<dim3(BATCH / 128, 2), 256>>>(context, b_in);
    rollout<<<NCTA, TPB, smem_bytes>>>(out, T, last_pose, W_in, W_out, b_out);
}

// round 10
// speedup vs baseline: 1.9892x; 1.2692x over previous
#include <cuda_runtime.h>
#include <cuda_fp16.h>
#include <math.h>
#include <stdint.h>

#define BATCH 4096
#define POSED 13
#define HID 256
#define IN_DIM 269
#define NCTA 128
#define TPB 384
#define GN 16            // n-groups (hidden-dim groups of 16)

// ------------------------- device globals ------------------------------------
__device__ __align__(16) __half d_A2[2][BATCH][1024];   // [xh|hh|xl|hl] fp16
__device__ __align__(16) float d_h[BATCH * HID];
__device__ __align__(16) float d_cproj[BATCH * HID];
__device__ __align__(16) __half d_Wrz_h[512 * 512];     // rz rows x [Wih|Whh] cols, fp16
__device__ __align__(16) __half d_Win_h[256 * 256];     // i_n rows of W_ih
__device__ __align__(16) __half d_Whn_h[256 * 256];     // h_n rows of W_hh
__device__ __align__(16) float d_Wctx[256 * 256];
__device__ float d_biasv[1024];
__device__ unsigned g_barcnt;

// ------------------------- helpers -------------------------------------------
__device__ __forceinline__ uint32_t smem_u32(const void* p) {
    uint32_t a;
    asm("{ .reg .u64 t; cvta.to.shared.u64 t, %1; cvt.u32.u64 %0, t; }" : "=r"(a) : "l"(p));
    return a;
}
__device__ __forceinline__ void cp16(uint32_t dst, const void* src) {
    asm volatile("cp.async.cg.shared.global [%0], [%1], 16;" :: "r"(dst), "l"(src) : "memory");
}
#define CP_COMMIT() asm volatile("cp.async.commit_group;" ::: "memory")
#define CP_WAIT1()  asm volatile("cp.async.wait_group 1;" ::: "memory")
#define CP_WAIT0()  asm volatile("cp.async.wait_group 0;" ::: "memory")

__device__ __forceinline__ void fp16_split(float v, __half& hi, __half& lo) {
    hi = __float2half_rn(v);
    lo = __float2half_rn(v - __half2float(hi));
}
__device__ __forceinline__ void mma_fp16(float* acc, const uint32_t* a, uint32_t b0, uint32_t b1) {
    asm volatile(
        "mma.sync.aligned.m16n8k16.row.col.f32.f16.f16.f32 "
        "{%0,%1,%2,%3}, {%4,%5,%6,%7}, {%8,%9}, {%0,%1,%2,%3};"
        : "+f"(acc[0]), "+f"(acc[1]), "+f"(acc[2]), "+f"(acc[3])
        : "r"(a[0]), "r"(a[1]), "r"(a[2]), "r"(a[3]), "r"(b0), "r"(b1));
}
__device__ __forceinline__ void ldm4(uint32_t* f, uint32_t addr) {
    asm volatile("ldmatrix.sync.aligned.m8n8.x4.shared.b16 {%0,%1,%2,%3}, [%4];"
                 : "=r"(f[0]), "=r"(f[1]), "=r"(f[2]), "=r"(f[3]) : "r"(addr));
}

// ------------------------- smem layout ---------------------------------------
struct Smem {
    __half sA[2][32][1032];          // staged A pair (32 rows x 1024 + pad), 2064B rows
    float g2[2][12][16][16];         // per-warp partials [mtile][warp][row][2 n8-tiles x 8]
    float wp[256][14];               // W_in[:, :13]
    float wout[13][256];
    float cproj[32][256];            // phase-2 rows
    float pose[32][14];
    float sbias[4][16];
};

// ------------------------- prep ----------------------------------------------
__global__ void prep_kernel(const float* __restrict__ W_ih, const float* __restrict__ W_hh,
                            const float* __restrict__ b_ih, const float* __restrict__ b_hh,
                            const float* __restrict__ W_in) {
    int i = blockIdx.x * blockDim.x + threadIdx.x;
    if (i == 0) g_barcnt = 0u;
    if (i < 512 * 512) {
        int n = i >> 9, k = i & 511;
        float w = (k < 256) ? W_ih[n * 256 + k] : W_hh[n * 256 + (k - 256)];
        d_Wrz_h[i] = __float2half_rn(w);
    }
    if (i < 256 * 256) {
        int n = i >> 8, k = i & 255;
        d_Win_h[i] = __float2half_rn(W_ih[(512 + n) * 256 + k]);
        d_Whn_h[i] = __float2half_rn(W_hh[(512 + n) * 256 + k]);
        d_Wctx[i] = W_in[n * IN_DIM + POSED + k];
    }
    if (i < 1024) {
        d_biasv[i] = (i < 512) ? (b_ih[i] + b_hh[i])
                   : (i < 768) ? b_ih[i]
                               : b_hh[i - 256];
    }
}

// ------------------------- fp32 GEMM (one-time cproj) ------------------------
__global__ __launch_bounds__(256, 2) void cproj_gemm(const float* __restrict__ context,
                                                     const float* __restrict__ b_in) {
    __shared__ float As[2][16][132];
    __shared__ float Ws[2][16][132];
    const int tid = threadIdx.x;
    const int ty = tid >> 4, tx = tid & 15;
    const int r0 = tid >> 2, kv = (tid & 3) << 2;
    const int m0 = blockIdx.x * 128;
    const int y = blockIdx.y;
    const float* A = context;
    const float* Wt = d_Wctx + y * 128 * 256;
    const float* biasp = b_in + y * 128;
    float* Cp = d_cproj + y * 128;

    float acc[8][8];
#pragma unroll
    for (int i = 0; i < 8; i++)
#pragma unroll
        for (int j = 0; j < 8; j++) acc[i][j] = 0.f;

    const float* Ar0 = A + (size_t)(m0 + r0) * 256 + kv;
    const float* Ar1 = A + (size_t)(m0 + 64 + r0) * 256 + kv;
    const float* Wr0 = Wt + (size_t)r0 * 256 + kv;
    const float* Wr1 = Wt + (size_t)(64 + r0) * 256 + kv;

    float4 pa0 = *(const float4*)Ar0, pa1 = *(const float4*)Ar1;
    float4 pw0 = *(const float4*)Wr0, pw1 = *(const float4*)Wr1;
    As[0][kv+0][r0]=pa0.x; As[0][kv+1][r0]=pa0.y; As[0][kv+2][r0]=pa0.z; As[0][kv+3][r0]=pa0.w;
    As[0][kv+0][64+r0]=pa1.x; As[0][kv+1][64+r0]=pa1.y; As[0][kv+2][64+r0]=pa1.z; As[0][kv+3][64+r0]=pa1.w;
    Ws[0][kv+0][r0]=pw0.x; Ws[0][kv+1][r0]=pw0.y; Ws[0][kv+2][r0]=pw0.z; Ws[0][kv+3][r0]=pw0.w;
    Ws[0][kv+0][64+r0]=pw1.x; Ws[0][kv+1][64+r0]=pw1.y; Ws[0][kv+2][64+r0]=pw1.z; Ws[0][kv+3][64+r0]=pw1.w;
    __syncthreads();

    for (int kt = 0; kt < 16; kt++) {
        const int buf = kt & 1;
        if (kt + 1 < 16) {
            int k0 = (kt + 1) << 4;
            pa0 = *(const float4*)(Ar0 + k0); pa1 = *(const float4*)(Ar1 + k0);
            pw0 = *(const float4*)(Wr0 + k0); pw1 = *(const float4*)(Wr1 + k0);
        }
#pragma unroll
        for (int kk = 0; kk < 16; kk++) {
            float4 a0 = *(const float4*)&As[buf][kk][ty*8];
            float4 a1 = *(const float4*)&As[buf][kk][ty*8+4];
            float4 w0 = *(const float4*)&Ws[buf][kk][tx*8];
            float4 w1 = *(const float4*)&Ws[buf][kk][tx*8+4];
            float af[8]={a0.x,a0.y,a0.z,a0.w,a1.x,a1.y,a1.z,a1.w};
            float wf[8]={w0.x,w0.y,w0.z,w0.w,w1.x,w1.y,w1.z,w1.w};
#pragma unroll
            for (int i = 0; i < 8; i++)
#pragma unroll
                for (int j = 0; j < 8; j++) acc[i][j] += af[i] * wf[j];
        }
        if (kt + 1 < 16) {
            const int nb = buf ^ 1;
            As[nb][kv+0][r0]=pa0.x; As[nb][kv+1][r0]=pa0.y; As[nb][kv+2][r0]=pa0.z; As[nb][kv+3][r0]=pa0.w;
            As[nb][kv+0][64+r0]=pa1.x; As[nb][kv+1][64+r0]=pa1.y; As[nb][kv+2][64+r0]=pa1.z; As[nb][kv+3][64+r0]=pa1.w;
            Ws[nb][kv+0][r0]=pw0.x; Ws[nb][kv+1][r0]=pw0.y; Ws[nb][kv+2][r0]=pw0.z; Ws[nb][kv+3][r0]=pw0.w;
            Ws[nb][kv+0][64+r0]=pw1.x; Ws[nb][kv+1][64+r0]=pw1.y; Ws[nb][kv+2][64+r0]=pw1.z; Ws[nb][kv+3][64+r0]=pw1.w;
            __syncthreads();
        }
    }
#pragma unroll
    for (int i = 0; i < 8; i++) {
        float* crow = Cp + (size_t)(m0 + ty*8 + i) * HID + tx*8;
        float4 b0 = *(const float4*)&biasp[tx*8];
        float4 b1 = *(const float4*)&biasp[tx*8+4];
        *(float4*)crow = make_float4(acc[i][0]+b0.x, acc[i][1]+b0.y, acc[i][2]+b0.z, acc[i][3]+b0.w);
        *(float4*)(crow+4) = make_float4(acc[i][4]+b1.x, acc[i][5]+b1.y, acc[i][6]+b1.z, acc[i][7]+b1.w);
    }
}

// ------------------------- persistent rollout kernel -------------------------
__global__ __launch_bounds__(TPB, 1) void rollout(
    float* __restrict__ out, int T,
    const float* __restrict__ last_pose,
    const float* __restrict__ W_in,
    const float* __restrict__ W_out,
    const float* __restrict__ b_out)
{
    extern __shared__ char smem_raw[];
    Smem* S = (Smem*)smem_raw;

    const int tid = threadIdx.x;
    const int w = tid >> 5;
    const int lane = tid & 31;
    const int cn = blockIdx.x & (GN - 1);
    const int cb = blockIdx.x >> 4;
    const int prow0 = blockIdx.x * 32;      // phase-2 rows

    // -------- persistent smem loads --------
    for (int i = tid; i < 256 * 13; i += TPB)
        S->wp[i / 13][i % 13] = W_in[(size_t)(i / 13) * IN_DIM + (i % 13)];
    for (int i = tid; i < 13 * 256; i += TPB)
        S->wout[i >> 8][i & 255] = W_out[i];
    for (int i = tid; i < 32 * 256; i += TPB)
        S->cproj[i >> 8][i & 255] = d_cproj[(size_t)(prow0 + (i >> 8)) * 256 + (i & 255)];
    if (tid < 64) S->sbias[tid >> 4][tid & 15] = d_biasv[(tid >> 4) * 256 + cn * 16 + (tid & 15)];
    for (int i = tid; i < 32 * 13; i += TPB)
        S->pose[i / 13][i % 13] = last_pose[(size_t)(prow0 + i / 13) * 13 + (i % 13)];

    // -------- warp classes + B-register prologue (32 regs/warp) --------------
    // rz warps 0..7: P = w>>2 (dim-half), side = (w>>1)&1 (0=x,1=h), half = w&1
    //   (k-half within side). n8t 0 = r rows P*8.., n8t 1 = z rows.
    // warps 8,9: i_n (x side), half = w-8, n8t = dim tile 0/1.
    // warps 10,11: h_n (h side), half = w-10.
    // Each warp: 8 s-steps; per s: A hi-frag + A lo-frag (same B for both).
    uint32_t breg[2][16];
    int hi_seg;
    if (w < 8) {
        const int P = w >> 2, side = (w >> 1) & 1, half = w & 1;
        hi_seg = side * 256 + half * 128;
#pragma unroll
        for (int n8t = 0; n8t < 2; n8t++) {
            int nrow = (n8t == 0) ? (cn * 16 + P * 8) : (256 + cn * 16 + P * 8);
            const __half* rowp = d_Wrz_h + (size_t)(nrow + (lane >> 2)) * 512
                               + side * 256 + half * 128 + (lane & 3) * 2;
#pragma unroll
            for (int s = 0; s < 8; s++) {
                breg[n8t][2 * s]     = *(const uint32_t*)(rowp + s * 16);
                breg[n8t][2 * s + 1] = *(const uint32_t*)(rowp + s * 16 + 8);
            }
        }
    } else {
        const int isI = (w < 10);
        const int half = isI ? (w - 8) : (w - 10);
        const __half* Wb = isI ? d_Win_h : d_Whn_h;
        hi_seg = (isI ? 0 : 256) + half * 128;
#pragma unroll
        for (int n8t = 0; n8t < 2; n8t++) {
            int nrow = cn * 16 + n8t * 8;
            const __half* rowp = Wb + (size_t)(nrow + (lane >> 2)) * 256
                               + half * 128 + (lane & 3) * 2;
#pragma unroll
            for (int s = 0; s < 8; s++) {
                breg[n8t][2 * s]     = *(const uint32_t*)(rowp + s * 16);
                breg[n8t][2 * s + 1] = *(const uint32_t*)(rowp + s * 16 + 8);
            }
        }
    }

    __syncthreads();

    unsigned bar_i = 0;
    auto gridbar = [&]() {
        __syncthreads();
        bar_i++;
        if (tid == 0) {
            __threadfence();
            atomicAdd(&g_barcnt, 1u);
            volatile unsigned* vc = (volatile unsigned*)&g_barcnt;
            unsigned target = bar_i * NCTA;
            while (*vc < target) { }
        }
        __syncthreads();
    };

    // x-projection for phase-2 rows into A buffer `buf`
    auto xwrite = [&](int buf) {
        for (int i = tid; i < 32 * 256; i += TPB) {
            int r = i >> 8, j = i & 255;
            float acc = S->cproj[r][j];
#pragma unroll
            for (int k = 0; k < POSED; k++) acc += S->wp[j][k] * S->pose[r][k];
            acc = fmaxf(acc, 0.f);
            __half hi, lo; fp16_split(acc, hi, lo);
            __half* Ar = d_A2[buf][prow0 + r];
            Ar[j] = hi;
            Ar[512 + j] = lo;
        }
    };

    // -------- phase 0: h=0, write A buf0 --------
    {
        __half z16 = __float2half_rn(0.f);
        for (int i = tid; i < 32 * 256; i += TPB) {
            int r = i >> 8, j = i & 255;
            d_h[(size_t)(prow0 + r) * 256 + j] = 0.f;
            __half* Ar = d_A2[0][prow0 + r];
            Ar[256 + j] = z16;
            Ar[768 + j] = z16;
        }
        xwrite(0);
    }
    gridbar();

    // -------- time loop --------
    for (int t = 0; t < T; t++) {
        const int rbuf = t & 1;
        const int wbufA = (t + 1) & 1;
        const __half* Abase = &d_A2[rbuf][cb * 512][0];

        auto load_pair = [&](int p, int buf) {
            const __half* src = Abase + (size_t)p * 32 * 1024;
            for (int idx = tid; idx < 4096; idx += TPB) {
                int r = idx >> 7, c = idx & 127;
                cp16(smem_u32(&S->sA[buf][r][c * 8]), src + (size_t)r * 1024 + c * 8);
            }
            CP_COMMIT();
        };

        load_pair(0, 0);

        for (int p = 0; p < 16; p++) {
            const int buf = p & 1;
            if (p + 1 < 16) { load_pair(p + 1, buf ^ 1); CP_WAIT1(); }
            else            { CP_WAIT0(); }
            __syncthreads();   // sA[buf] ready; prev gate pass done (g2 reusable)

            const int m0g = cb * 512 + p * 32;

            // ---- prefetch h_prev for this tile's gate elems (hide latency) ----
            float hp0, hp1 = 0.f;
            {
                int i = tid;
                int grow = m0g + (i >> 8) * 16 + ((i & 255) >> 4);
                hp0 = __ldcg(&d_h[(size_t)grow * 256 + cn * 16 + (i & 15)]);
            }
            if (tid < 128) {
                int i = tid + TPB;
                int grow = m0g + (i >> 8) * 16 + ((i & 255) >> 4);
                hp1 = __ldcg(&d_h[(size_t)grow * 256 + cn * 16 + (i & 15)]);
            }

            // ---- mma: 8 iters x (A hi + A lo frags, shared B), 2 n8-tiles ----
            float acc[2][2][4];
#pragma unroll
            for (int a = 0; a < 2; a++)
#pragma unroll
                for (int m = 0; m < 2; m++)
#pragma unroll
                    for (int v = 0; v < 4; v++) acc[a][m][v] = 0.f;

            uint32_t abase = smem_u32(&S->sA[buf][0][0])
                           + (uint32_t)(lane & 15) * 2064u + (uint32_t)((lane >> 4) * 16);
#pragma unroll
            for (int s = 0; s < 8; s++) {
                uint32_t adh = abase + (uint32_t)((hi_seg + s * 16) * 2);
                uint32_t adl = adh + 1024u;                    // lo seg = hi + 512 halves
                uint32_t fh0[4], fh1[4], fl0[4], fl1[4];
                ldm4(fh0, adh);
                ldm4(fh1, adh + 16u * 2064u);
                ldm4(fl0, adl);
                ldm4(fl1, adl + 16u * 2064u);
#pragma unroll
                for (int n8t = 0; n8t < 2; n8t++) {
                    uint32_t b0 = breg[n8t][2 * s], b1 = breg[n8t][2 * s + 1];
                    mma_fp16(acc[n8t][0], fh0, b0, b1);
                    mma_fp16(acc[n8t][1], fh1, b0, b1);
                    mma_fp16(acc[n8t][0], fl0, b0, b1);
                    mma_fp16(acc[n8t][1], fl1, b0, b1);
                }
            }

            // ---- write per-warp partials (deterministic; no atomics) ----
            {
                int gr = lane >> 2, gc = (lane & 3) << 1;
#pragma unroll
                for (int n8t = 0; n8t < 2; n8t++)
#pragma unroll
                    for (int m = 0; m < 2; m++) {
                        *(float2*)&S->g2[m][w][gr][n8t * 8 + gc] =
                            make_float2(acc[n8t][m][0], acc[n8t][m][1]);
                        *(float2*)&S->g2[m][w][gr + 8][n8t * 8 + gc] =
                            make_float2(acc[n8t][m][2], acc[n8t][m][3]);
                    }
            }
            __syncthreads();   // partials complete; sA[buf] free

            // ---- gates for 32 rows x 16 dims (fixed-order sums) ----
#pragma unroll
            for (int rep = 0; rep < 2; rep++) {
                int i = tid + rep * TPB;
                if (rep == 1 && tid >= 128) break;
                float hp = (rep == 0) ? hp0 : hp1;
                int mt = i >> 8, sub = i & 255;
                int r16 = sub >> 4, dl = sub & 15;
                int P4 = (dl >> 3) * 4, c = dl & 7;
                int grow = m0g + mt * 16 + r16;
                int dim = cn * 16 + dl;
                float sr = S->g2[mt][P4][r16][c]     + S->g2[mt][P4 + 1][r16][c]
                         + S->g2[mt][P4 + 2][r16][c] + S->g2[mt][P4 + 3][r16][c]
                         + S->sbias[0][dl];
                float sz = S->g2[mt][P4][r16][8 + c]     + S->g2[mt][P4 + 1][r16][8 + c]
                         + S->g2[mt][P4 + 2][r16][8 + c] + S->g2[mt][P4 + 3][r16][8 + c]
                         + S->sbias[1][dl];
                float in_ = S->g2[mt][8][r16][dl]  + S->g2[mt][9][r16][dl]  + S->sbias[2][dl];
                float hn  = S->g2[mt][10][r16][dl] + S->g2[mt][11][r16][dl] + S->sbias[3][dl];
                float r = 1.f / (1.f + expf(-sr));
                float z = 1.f / (1.f + expf(-sz));
                float n = tanhf(in_ + r * hn);
                float hnew = (1.f - z) * n + z * hp;
                d_h[(size_t)grow * 256 + dim] = hnew;
                __half hi, lo; fp16_split(hnew, hi, lo);
                __half* Ar = d_A2[wbufA][grow];
                Ar[256 + dim] = hi;
                Ar[768 + dim] = lo;
            }
            // next iteration's first __syncthreads protects g2 reuse
        }
        gridbar();

        // -------- phase 2: pose update + next x --------
        for (int rloc = w; rloc < 32; rloc += 12) {
            int grow = prow0 + rloc;
            const float* hrow = d_h + (size_t)grow * 256;
            float hreg[8];
#pragma unroll
            for (int i = 0; i < 8; i++) hreg[i] = __ldcg(hrow + lane + 32 * i);
#pragma unroll
            for (int pp = 0; pp < POSED; pp++) {
                float dp = 0.f;
#pragma unroll
                for (int i = 0; i < 8; i++) dp += S->wout[pp][lane + 32 * i] * hreg[i];
#pragma unroll
                for (int o = 16; o > 0; o >>= 1) dp += __shfl_down_sync(0xffffffffu, dp, o);
                if (lane == 0) S->pose[rloc][pp] += dp + b_out[pp];
            }
            __syncwarp();
            if (lane == 0) {
                float q = sqrtf(S->pose[rloc][3] * S->pose[rloc][3] +
                                S->pose[rloc][4] * S->pose[rloc][4] +
                                S->pose[rloc][5] * S->pose[rloc][5] +
                                S->pose[rloc][6] * S->pose[rloc][6]);
                q = fmaxf(q, 1e-12f);
                S->pose[rloc][3] /= q;
                S->pose[rloc][4] /= q;
                S->pose[rloc][5] /= q;
                S->pose[rloc][6] /= q;
                float* op = out + ((size_t)grow * T + t) * POSED;
#pragma unroll
                for (int pp = 0; pp < POSED; pp++) op[pp] = S->pose[rloc][pp];
            }
        }
        __syncthreads();
        xwrite(wbufA);
        gridbar();
    }
}

// ------------------------- launch --------------------------------------------
extern "C" void kernel_launch(void* const* d_in, const int* in_sizes, int n_in,
                              void* d_out, int out_size)
{
    const float* last_pose = (const float*)d_in[0];
    const float* context   = (const float*)d_in[1];
    const float* W_in  = (const float*)d_in[3];
    const float* b_in  = (const float*)d_in[4];
    const float* W_ih  = (const float*)d_in[5];
    const float* b_ih  = (const float*)d_in[6];
    const float* W_hh  = (const float*)d_in[7];
    const float* b_hh  = (const float*)d_in[8];
    const float* W_out = (const float*)d_in[9];
    const float* b_out = (const float*)d_in[10];
    float* out = (float*)d_out;

    const int T = out_size / (BATCH * POSED);
    const int smem_bytes = (int)sizeof(Smem);

    cudaFuncSetAttribute(rollout, cudaFuncAttributeMaxDynamicSharedMemorySize, smem_bytes);

    prep_kernel<<<(512 * 512 + 255) / 256, 256>>>(W_ih, W_hh, b_ih, b_hh, W_in);
    cproj_gemm<<<dim3(BATCH / 128, 2), 256>>>(context, b_in);
    rollout<<<NCTA, TPB, smem_bytes>>>(out, T, last_pose, W_in, W_out, b_out);
}